// round 1
// baseline (speedup 1.0000x reference)
#include <cuda_runtime.h>
#include <cstdint>
#include <cstdio>

// Problem constants (fixed by setup_inputs)
#define B_   16
#define QN   75
#define C_   640
#define HW   25
#define MS   625    // way*shot*hw = 5*5*25
#define MQ   25
#define NTOT (B_*QN)   // 1200

// ---------------- scratch (device globals: allocation-free) ----------------
__device__ float g_qT[(size_t)B_*QN*HW*C_];   // [b*1875 + r][640]  (row r = q*25+p)
__device__ float g_sT[(size_t)B_*MS*C_];      // [b*625 + j][640]   (j = sidx*25+pix)
__device__ float g_qInv[B_*QN*HW];            // 1/norm per query pixel (with eps semantics)
__device__ float g_sInv[B_*MS];               // 1/norm per support pixel
__device__ float g_S[(size_t)NTOT*MQ*MS];     // S[n][25][625] = cosine sims

// =====================================================================
// K1: transpose (c-major strided -> row-contiguous) + squared-norm
// One block per source "image" (640 x 25 pixels). mode 0: support, 1: query.
// =====================================================================
__global__ __launch_bounds__(256) void transpose_norm_kernel(const float* __restrict__ src, int mode)
{
    float* dst = mode ? g_qT  : g_sT;
    float* inv = mode ? g_qInv : g_sInv;

    __shared__ float tile[320*25];   // 32 KB chunk: 320 channels x 25 pixels
    const int t = threadIdx.x, w = t >> 5, lane = t & 31;
    const size_t base  = (size_t)blockIdx.x * (C_*HW);
    const size_t drow0 = (size_t)blockIdx.x * HW;

    float ss[4] = {0.f, 0.f, 0.f, 0.f};
    for (int ch = 0; ch < 2; ch++) {
        const int c0 = ch * 320;
        __syncthreads();
        // coalesced load of [c0:c0+320) x 25 contiguous region
        for (int idx = t; idx < 8000; idx += 256)
            tile[idx] = src[base + (size_t)c0*HW + idx];
        __syncthreads();
#pragma unroll
        for (int slot = 0; slot < 4; slot++) {
            int p = w + slot*8;
            if (p < 25) {
                float s = 0.f;
                float* drow = dst + (drow0 + p)*C_ + c0;
                for (int c = lane; c < 320; c += 32) {
                    float v = tile[c*25 + p];   // stride 25: conflict-free (coprime w/ 32)
                    s += v*v;
                    drow[c] = v;                // coalesced write
                }
                ss[slot] += s;
            }
        }
    }
#pragma unroll
    for (int slot = 0; slot < 4; slot++) {
        int p = w + slot*8;
        if (p < 25) {
            float s = ss[slot];
            for (int o = 16; o; o >>= 1) s += __shfl_down_sync(0xffffffffu, s, o);
            if (lane == 0) {
                // exact replica of the reference double-normalization:
                // v / max(n,1e-12) then / (1e-16 + n/max(n,1e-12))
                float nn = sqrtf(s);
                float d1 = fmaxf(nn, 1e-12f);
                inv[drow0 + p] = 1.0f / (d1 * (1e-16f + nn/d1));
            }
        }
    }
}

// =====================================================================
// K2: batched SGEMM   S_b(1875x625) = qT_b(1875x640) * sT_b(640x625)^T
// 128x128 CTA tiles, BK=8, 8x8 register tiles, double-buffered smem,
// norms applied in epilogue.
// =====================================================================
#define BM 128
#define BN 128
#define BK 8

__global__ __launch_bounds__(256) void gemm_kernel()
{
    __shared__ __align__(16) float As[2][BK][BM+4];
    __shared__ __align__(16) float Bs[2][BK][BN+4];

    const int b  = blockIdx.z;
    const int t  = threadIdx.x;
    const int lrow = t >> 1;              // 0..127
    const int lk   = (t & 1) << 2;        // 0 or 4
    const int tx = t & 15, ty = t >> 4;   // 16x16 thread grid

    const float* A  = g_qT + (size_t)b*1875*C_;
    const float* Bp = g_sT + (size_t)b*625*C_;
    const int giA = blockIdx.y*BM + lrow;
    const int gjB = blockIdx.x*BN + lrow;
    const bool av = (giA < 1875);
    const bool bv = (gjB < 625);

    float acc[8][8];
#pragma unroll
    for (int u = 0; u < 8; u++)
#pragma unroll
        for (int v = 0; v < 8; v++) acc[u][v] = 0.f;

    float4 na = make_float4(0,0,0,0), nb = make_float4(0,0,0,0);
    if (av) na = *(const float4*)(A  + (size_t)giA*C_ + lk);
    if (bv) nb = *(const float4*)(Bp + (size_t)gjB*C_ + lk);
    As[0][lk+0][lrow]=na.x; As[0][lk+1][lrow]=na.y; As[0][lk+2][lrow]=na.z; As[0][lk+3][lrow]=na.w;
    Bs[0][lk+0][lrow]=nb.x; Bs[0][lk+1][lrow]=nb.y; Bs[0][lk+2][lrow]=nb.z; Bs[0][lk+3][lrow]=nb.w;
    __syncthreads();

    int buf = 0;
    for (int kc = 0; kc < C_/BK; kc++) {
        const bool more = (kc < C_/BK - 1);
        if (more) {
            const int k0 = (kc+1)*BK;
            na = make_float4(0,0,0,0); nb = make_float4(0,0,0,0);
            if (av) na = *(const float4*)(A  + (size_t)giA*C_ + k0 + lk);
            if (bv) nb = *(const float4*)(Bp + (size_t)gjB*C_ + k0 + lk);
        }
#pragma unroll
        for (int k = 0; k < BK; k++) {
            float4 a0 = *(const float4*)&As[buf][k][ty*8];
            float4 a1 = *(const float4*)&As[buf][k][ty*8+4];
            float4 b0 = *(const float4*)&Bs[buf][k][tx*8];
            float4 b1 = *(const float4*)&Bs[buf][k][tx*8+4];
            float ar[8] = {a0.x,a0.y,a0.z,a0.w,a1.x,a1.y,a1.z,a1.w};
            float br[8] = {b0.x,b0.y,b0.z,b0.w,b1.x,b1.y,b1.z,b1.w};
#pragma unroll
            for (int u = 0; u < 8; u++)
#pragma unroll
                for (int v = 0; v < 8; v++) acc[u][v] += ar[u]*br[v];
        }
        if (more) {
            const int nbuf = buf ^ 1;
            As[nbuf][lk+0][lrow]=na.x; As[nbuf][lk+1][lrow]=na.y; As[nbuf][lk+2][lrow]=na.z; As[nbuf][lk+3][lrow]=na.w;
            Bs[nbuf][lk+0][lrow]=nb.x; Bs[nbuf][lk+1][lrow]=nb.y; Bs[nbuf][lk+2][lrow]=nb.z; Bs[nbuf][lk+3][lrow]=nb.w;
        }
        __syncthreads();
        buf ^= 1;
    }

    const float* qInvB = g_qInv + (size_t)b*1875;
    const float* sInvB = g_sInv + (size_t)b*625;
    float* Cout = g_S + (size_t)b*1875*625;
#pragma unroll
    for (int u = 0; u < 8; u++) {
        const int r = blockIdx.y*BM + ty*8 + u;
        if (r >= 1875) continue;
        const float qv = qInvB[r];
#pragma unroll
        for (int v = 0; v < 8; v++) {
            const int cj = blockIdx.x*BN + tx*8 + v;
            if (cj < 625) Cout[(size_t)r*625 + cj] = acc[u][v] * qv * sInvB[cj];
        }
    }
}

// =====================================================================
// K3: per-n postprocessing. One CTA per n (1200 CTAs), 133KB dyn smem.
// Softmaxes -> G = C*B (25x25) -> Neumann solve of (I - 0.25G)x = rhs
// -> class sums. Exact block-elimination of the reference's 650x650 solve.
// =====================================================================
#define POST_FLOATS 33268
#define POST_BYTES  (POST_FLOATS*4)

__global__ __launch_bounds__(256) void post_kernel(float* __restrict__ out)
{
    extern __shared__ float sm[];
    float* S0     = sm;            // 15625: S, then overwritten with Tqs[i][j]
    float* T1     = sm + 15625;    // 15625: Tsq[i][j]
    float* cmaxS  = sm + 31250;    // 625
    float* cinvS  = sm + 31875;    // 625
    float* rmaxS  = sm + 32500;    // 25
    float* rinvS  = sm + 32525;    // 25
    float* rhsS   = sm + 32550;    // 25
    float* Gm     = sm + 32576;    // 25*26
    float* xs     = sm + 33226;    // 32
    float* clsS   = sm + 33258;    // 8
    float* denomS = sm + 33266;    // 1

    const int n = blockIdx.x;
    const int t = threadIdx.x, w = t >> 5, lane = t & 31;

    const float* Sg = g_S + (size_t)n * 15625;
    for (int idx = t; idx < 15625; idx += 256) S0[idx] = Sg[idx];
    __syncthreads();

    // ---- row softmax stats (gamma=20 over j) ----
    for (int i = w; i < 25; i += 8) {
        const float* row = S0 + i*625;
        float m = -1e30f;
        for (int j = lane; j < 625; j += 32) m = fmaxf(m, row[j]);
        for (int o = 16; o; o >>= 1) m = fmaxf(m, __shfl_xor_sync(0xffffffffu, m, o));
        float s = 0.f;
        for (int j = lane; j < 625; j += 32) s += __expf(20.f*(row[j] - m));
        for (int o = 16; o; o >>= 1) s += __shfl_xor_sync(0xffffffffu, s, o);
        if (lane == 0) { rmaxS[i] = m; rinvS[i] = 1.f/s; }
    }
    // ---- col softmax stats (gamma2=10 over i) ----
    for (int j = t; j < 625; j += 256) {
        float m = -1e30f;
        for (int i = 0; i < 25; i++) m = fmaxf(m, S0[i*625 + j]);
        float s = 0.f;
        for (int i = 0; i < 25; i++) s += __expf(10.f*(S0[i*625 + j] - m));
        cmaxS[j] = m; cinvS[j] = 1.f/s;
    }
    __syncthreads();

    // ---- materialize Tsq (into T1) and Tqs (into S0 in place) ----
    for (int i = 0; i < 25; i++) {
        const float rm = rmaxS[i], ri = rinvS[i];
        for (int j = t; j < 625; j += 256) {
            const float v = S0[i*625 + j];
            T1[i*625 + j] = __expf(20.f*(v - rm)) * ri;
            S0[i*625 + j] = __expf(10.f*(v - cmaxS[j])) * cinvS[j];
        }
    }
    __syncthreads();

    // ---- rhs[i] = 1 + 0.5 * sum_j Tqs[i][j]  ( = 1 + 0.5*(C 1)[i] ) ----
    for (int i = w; i < 25; i += 8) {
        const float* row = S0 + i*625;
        float s = 0.f;
        for (int j = lane; j < 625; j += 32) s += row[j];
        for (int o = 16; o; o >>= 1) s += __shfl_xor_sync(0xffffffffu, s, o);
        if (lane == 0) rhsS[i] = 1.f + 0.5f*s;
    }
    // ---- G[i][i'] = sum_j Tqs[i][j]*Tsq[i'][j] : 5x5 warp tiles ----
    for (int tile = w; tile < 25; tile += 8) {
        const int i0 = (tile/5)*5, p0 = (tile%5)*5;
        float acc[25];
#pragma unroll
        for (int z = 0; z < 25; z++) acc[z] = 0.f;
        for (int j = lane; j < 625; j += 32) {
            float a[5], c[5];
#pragma unroll
            for (int z = 0; z < 5; z++) { a[z] = S0[(i0+z)*625 + j]; c[z] = T1[(p0+z)*625 + j]; }
#pragma unroll
            for (int u = 0; u < 5; u++)
#pragma unroll
                for (int v = 0; v < 5; v++) acc[u*5+v] += a[u]*c[v];
        }
#pragma unroll
        for (int z = 0; z < 25; z++) {
            float s = acc[z];
            for (int o = 16; o; o >>= 1) s += __shfl_xor_sync(0xffffffffu, s, o);
            if (lane == 0) Gm[(i0 + z/5)*26 + (p0 + z%5)] = s;
        }
    }
    __syncthreads();

    // ---- Neumann solve (I - 0.25 G) x = rhs ; rho(0.25G) <= 0.25 ----
    if (w == 0) {
        float gr[25];
        const float rh = (lane < 25) ? rhsS[lane] : 0.f;
        if (lane < 25) {
#pragma unroll
            for (int p = 0; p < 25; p++) gr[p] = Gm[lane*26 + p];
        }
        float xi = rh;
        xs[lane] = xi;
        for (int it = 0; it < 16; it++) {
            __syncwarp();
            float s = 0.f;
            if (lane < 25) {
#pragma unroll
                for (int p = 0; p < 25; p++) s += gr[p]*xs[p];
            }
            __syncwarp();
            xi = (lane < 25) ? rh + 0.25f*s : 0.f;
            xs[lane] = xi;
        }
        __syncwarp();
        float dv = xi;  // lanes >=25 contribute 0
        for (int o = 16; o; o >>= 1) dv += __shfl_xor_sync(0xffffffffu, dv, o);
        if (lane == 0) denomS[0] = dv;
    }
    __syncthreads();

    // ---- predicts[w] = sum_{j in class w} (B x)_j / sum_i x_i ----
    if (w < 5) {
        float s = 0.f;
        for (int jj = lane; jj < 125; jj += 32) {
            const int j = w*125 + jj;
            float y = 0.f;
#pragma unroll
            for (int i = 0; i < 25; i++) y += T1[i*625 + j]*xs[i];
            s += y;
        }
        for (int o = 16; o; o >>= 1) s += __shfl_xor_sync(0xffffffffu, s, o);
        if (lane == 0) clsS[w] = s;
    }
    __syncthreads();
    if (t < 5) out[n*5 + t] = clsS[t] / denomS[0];
}

// =====================================================================
extern "C" void kernel_launch(void* const* d_in, const int* in_sizes, int n_in,
                              void* d_out, int out_size)
{
    const float* query   = (const float*)d_in[0];
    const float* support = (const float*)d_in[1];
    float* out = (float*)d_out;

    // idempotent, called every time (no static guards)
    cudaFuncSetAttribute(post_kernel, cudaFuncAttributeMaxDynamicSharedMemorySize, POST_BYTES);

    transpose_norm_kernel<<<B_*25, 256>>>(support, 0);   // -> g_sT, g_sInv
    transpose_norm_kernel<<<B_*QN, 256>>>(query,   1);   // -> g_qT, g_qInv

    dim3 gg(5, 15, B_);   // j-tiles x i-tiles x batch
    gemm_kernel<<<gg, 256>>>();

    post_kernel<<<NTOT, 256, POST_BYTES>>>(out);
}

// round 8
// speedup vs baseline: 2.5124x; 2.5124x over previous
#include <cuda_runtime.h>
#include <cstdint>

// Problem constants (fixed by setup_inputs)
#define B_   16
#define QN   75
#define C_   640
#define HW   25
#define MS   625
#define NTOT (B_*QN)      // 1200
#define MPAD 1920         // 15*128 padded query rows per batch
#define NPAD 640          // 5*128 padded support rows per batch

// ---------------- scratch (device globals: allocation-free, zero-init) -----
__device__ __align__(16) float g_qT[(size_t)B_*MPAD*C_];    // tf32-rounded, row-major [row][640]
__device__ __align__(16) float g_sT[(size_t)B_*NPAD*C_];    // tf32-rounded
__device__ __align__(16) float g_qInv[B_*QN*HW];
__device__ __align__(16) float g_sInv[B_*MS];
__device__ __align__(16) float g_S[(size_t)NTOT*HW*MS];     // S[n][25][625] cosine sims

// ======================= helpers ===========================================
__device__ __forceinline__ uint32_t smem_u32(const void* p) {
    uint32_t a;
    asm("{ .reg .u64 t; cvta.to.shared.u64 t, %1; cvt.u32.u64 %0, t; }" : "=r"(a) : "l"(p));
    return a;
}
__device__ __forceinline__ float to_tf32(float v) {
    uint32_t o;
    asm("cvt.rna.tf32.f32 %0, %1;" : "=r"(o) : "f"(v));
    return __uint_as_float(o);
}
__device__ __forceinline__ void cp16(uint32_t d, const void* s) {
    asm volatile("cp.async.cg.shared.global [%0], [%1], 16;" :: "r"(d), "l"(s));
}

// =====================================================================
// K1: transpose (c-major -> row-contiguous) + norm + tf32 rounding.
// One block per image. mode 0: support, 1: query.
// =====================================================================
__global__ __launch_bounds__(256) void transpose_norm_kernel(const float* __restrict__ src, int mode)
{
    __shared__ float tile[320*25];
    const int t = threadIdx.x, w = t >> 5, lane = t & 31;
    const int bi = blockIdx.x;
    const int imgs_per_b = mode ? QN : (MS/HW);     // 75 or 25
    const int b = bi / imgs_per_b, im = bi % imgs_per_b;
    const size_t base = (size_t)bi * (C_*HW);

    float* dst = mode ? g_qT : g_sT;
    float* inv = mode ? g_qInv : g_sInv;
    const size_t padrow0 = (size_t)b * (mode ? MPAD : NPAD) + (size_t)im * HW;
    const size_t invrow0 = (size_t)b * (mode ? (QN*HW) : MS) + (size_t)im * HW;

    float ss[4] = {0.f, 0.f, 0.f, 0.f};
    for (int ch = 0; ch < 2; ch++) {
        const int c0 = ch * 320;
        __syncthreads();
        for (int idx = t; idx < 8000; idx += 256)
            tile[idx] = src[base + (size_t)c0*HW + idx];
        __syncthreads();
#pragma unroll
        for (int slot = 0; slot < 4; slot++) {
            int p = w + slot*8;
            if (p < 25) {
                float s = 0.f;
                float* drow = dst + (padrow0 + p)*C_ + c0;
                for (int c = lane; c < 320; c += 32) {
                    float v = tile[c*25 + p];   // stride 25: conflict-free
                    s += v*v;
                    drow[c] = to_tf32(v);       // pre-round for mma.tf32
                }
                ss[slot] += s;
            }
        }
    }
#pragma unroll
    for (int slot = 0; slot < 4; slot++) {
        int p = w + slot*8;
        if (p < 25) {
            float s = ss[slot];
            for (int o = 16; o; o >>= 1) s += __shfl_down_sync(0xffffffffu, s, o);
            if (lane == 0) {
                // exact replica of reference double-normalization semantics
                float nn = sqrtf(s);
                float d1 = fmaxf(nn, 1e-12f);
                inv[invrow0 + p] = 1.0f / (d1 * (1e-16f + nn/d1));
            }
        }
    }
}

// =====================================================================
// K2: tf32 mma.sync GEMM.  S_b(1875x625) = qT_b * sT_b^T, fp32 accum.
// 128x128 CTA tile, BK=32, 8 warps (2x4), 64x32 warp tiles,
// cp.async double-buffered, smem stride 36 (conflict-free frag loads:
// address mod 32 banks = 4g + t4, all lanes distinct).
// =====================================================================
#define LDA 36
#define GSM_BYTES (4*128*LDA*4)   // 2 bufs x (A+B) x 128 rows x 36 floats = 73728

__global__ __launch_bounds__(256) void gemm_tf32_kernel()
{
    extern __shared__ float sm[];
    float* As = sm;                     // [2][128*LDA]
    float* Bs = sm + 2*128*LDA;         // [2][128*LDA]

    const int t = threadIdx.x;
    const int lane = t & 31, wid = t >> 5;
    const int warpM = wid >> 2, warpN = wid & 3;   // 2 x 4 warp grid
    const int g = lane >> 2, t4 = lane & 3;
    const int arow0 = blockIdx.y * 128, brow0 = blockIdx.x * 128;
    const int b = blockIdx.z;
    const int lrow = t >> 3, lc4 = t & 7;          // loader mapping

    const float* A  = g_qT + ((size_t)b*MPAD + arow0)*C_;
    const float* Bp = g_sT + ((size_t)b*NPAD + brow0)*C_;

    float acc[4][4][4];
#pragma unroll
    for (int i = 0; i < 4; i++)
#pragma unroll
        for (int j = 0; j < 4; j++)
#pragma unroll
            for (int k = 0; k < 4; k++) acc[i][j][k] = 0.f;

    auto issue = [&](int kc, int buf) {
        float* Ad = As + buf*(128*LDA);
        float* Bd = Bs + buf*(128*LDA);
        const float* Ag = A  + kc*32;
        const float* Bg = Bp + kc*32;
#pragma unroll
        for (int i = 0; i < 4; i++) {
            const int r = i*32 + lrow;
            cp16(smem_u32(Ad + r*LDA + lc4*4), Ag + (size_t)r*C_ + lc4*4);
            cp16(smem_u32(Bd + r*LDA + lc4*4), Bg + (size_t)r*C_ + lc4*4);
        }
        asm volatile("cp.async.commit_group;" ::: "memory");
    };

    issue(0, 0);
    issue(1, 1);

    for (int kc = 0; kc < 20; kc++) {
        if (kc < 19) asm volatile("cp.async.wait_group 1;" ::: "memory");
        else         asm volatile("cp.async.wait_group 0;" ::: "memory");
        __syncthreads();

        const float* Ab = As + (kc&1)*(128*LDA) + (warpM*64 + g)*LDA + t4;
        const float* Bb = Bs + (kc&1)*(128*LDA) + (warpN*32 + g)*LDA + t4;
#pragma unroll
        for (int ks = 0; ks < 4; ks++) {
            uint32_t af[4][4], bf[4][2];
#pragma unroll
            for (int mf = 0; mf < 4; mf++) {
                const float* p = Ab + mf*16*LDA + ks*8;
                af[mf][0] = __float_as_uint(p[0]);
                af[mf][1] = __float_as_uint(p[8*LDA]);
                af[mf][2] = __float_as_uint(p[4]);
                af[mf][3] = __float_as_uint(p[8*LDA + 4]);
            }
#pragma unroll
            for (int nf = 0; nf < 4; nf++) {
                const float* p = Bb + nf*8*LDA + ks*8;
                bf[nf][0] = __float_as_uint(p[0]);
                bf[nf][1] = __float_as_uint(p[4]);
            }
#pragma unroll
            for (int mf = 0; mf < 4; mf++)
#pragma unroll
                for (int nf = 0; nf < 4; nf++)
                    asm volatile(
                        "mma.sync.aligned.m16n8k8.row.col.f32.tf32.tf32.f32 "
                        "{%0,%1,%2,%3}, {%4,%5,%6,%7}, {%8,%9}, {%0,%1,%2,%3};"
                        : "+f"(acc[mf][nf][0]), "+f"(acc[mf][nf][1]),
                          "+f"(acc[mf][nf][2]), "+f"(acc[mf][nf][3])
                        : "r"(af[mf][0]), "r"(af[mf][1]), "r"(af[mf][2]), "r"(af[mf][3]),
                          "r"(bf[nf][0]), "r"(bf[nf][1]));
        }
        __syncthreads();
        if (kc + 2 < 20) issue(kc + 2, kc & 1);
    }

    // epilogue: apply the two inverse norms, write valid region of S
    const float* qInvB = g_qInv + b*1875;
    const float* sInvB = g_sInv + b*625;
    float* Cout = g_S + (size_t)b*1875*625;
#pragma unroll
    for (int mf = 0; mf < 4; mf++) {
#pragma unroll
        for (int rr = 0; rr < 2; rr++) {
            const int r = arow0 + warpM*64 + mf*16 + g + rr*8;
            if (r >= 1875) continue;
            const float qv = qInvB[r];
            float* orow = Cout + (size_t)r*625;
#pragma unroll
            for (int nf = 0; nf < 4; nf++) {
                const int c = brow0 + warpN*32 + nf*8 + 2*t4;
                if (c < 625)     orow[c]   = acc[mf][nf][rr*2+0] * qv * sInvB[c];
                if (c + 1 < 625) orow[c+1] = acc[mf][nf][rr*2+1] * qv * sInvB[c+1];
            }
        }
    }
}

// =====================================================================
// K3: per-n postprocessing, 512 threads, one exp per element.
// Softmaxes -> G = C*B (25x25) -> Neumann solve -> class sums.
// =====================================================================
#define PNT 512
#define PNW 16
#define POST_FLOATS 32640
#define POST_BYTES  (POST_FLOATS*4)

__global__ __launch_bounds__(PNT) void post_kernel(float* __restrict__ out)
{
    extern __shared__ float sm[];
    float* S0   = sm;            // 15625: e10 -> Tqs
    float* T1   = sm + 15625;    // 15625: e20 -> Tsq
    float* cinv = sm + 31250;    // 625
    float* rinv = sm + 31875;    // 32
    float* rhsS = sm + 31907;    // 32
    float* Gm   = sm + 31939;    // 650
    float* xs   = sm + 32589;    // 32
    float* clsS = sm + 32621;    // 8
    float* denomS = sm + 32629;  // 1

    const int n = blockIdx.x;
    const int t = threadIdx.x, w = t >> 5, lane = t & 31;

    // pass 1: load S, 1 exp per element (no max subtraction: |S|<=1 -> e^20 max)
    const float* Sg = g_S + (size_t)n * 15625;
    for (int idx = t; idx < 15625; idx += PNT) {
        const float v = Sg[idx];
        const float e10 = __expf(10.f * v);
        S0[idx] = e10;
        T1[idx] = e10 * e10;
    }
    __syncthreads();

    // row sums of e20 -> rinv
    for (int i = w; i < 25; i += PNW) {
        const float* row = T1 + i*625;
        float s = 0.f;
        for (int j = lane; j < 625; j += 32) s += row[j];
        for (int o = 16; o; o >>= 1) s += __shfl_xor_sync(0xffffffffu, s, o);
        if (lane == 0) rinv[i] = 1.f / s;
    }
    // col sums of e10 -> cinv
    for (int j = t; j < 625; j += PNT) {
        float s = 0.f;
#pragma unroll
        for (int i = 0; i < 25; i++) s += S0[i*625 + j];
        cinv[j] = 1.f / s;
    }
    __syncthreads();

    // normalize: T1 -> Tsq (row softmax, gamma 20), S0 -> Tqs (col softmax, gamma 10)
    for (int i = 0; i < 25; i++) {
        const float ri = rinv[i];
        for (int j = t; j < 625; j += PNT) {
            T1[i*625 + j] *= ri;
            S0[i*625 + j] *= cinv[j];
        }
    }
    __syncthreads();

    // rhs[i] = 1 + 0.5 * sum_j Tqs[i][j]
    for (int i = w; i < 25; i += PNW) {
        const float* row = S0 + i*625;
        float s = 0.f;
        for (int j = lane; j < 625; j += 32) s += row[j];
        for (int o = 16; o; o >>= 1) s += __shfl_xor_sync(0xffffffffu, s, o);
        if (lane == 0) rhsS[i] = 1.f + 0.5f*s;
    }
    // G[i][i'] = sum_j Tqs[i][j]*Tsq[i'][j] : 5x5 warp tiles
    for (int tile = w; tile < 25; tile += PNW) {
        const int i0 = (tile/5)*5, p0 = (tile%5)*5;
        float acc[25];
#pragma unroll
        for (int z = 0; z < 25; z++) acc[z] = 0.f;
        for (int j = lane; j < 625; j += 32) {
            float a[5], c[5];
#pragma unroll
            for (int z = 0; z < 5; z++) { a[z] = S0[(i0+z)*625 + j]; c[z] = T1[(p0+z)*625 + j]; }
#pragma unroll
            for (int u = 0; u < 5; u++)
#pragma unroll
                for (int v = 0; v < 5; v++) acc[u*5+v] += a[u]*c[v];
        }
#pragma unroll
        for (int z = 0; z < 25; z++) {
            float s = acc[z];
            for (int o = 16; o; o >>= 1) s += __shfl_xor_sync(0xffffffffu, s, o);
            if (lane == 0) Gm[(i0 + z/5)*26 + (p0 + z%5)] = s;
        }
    }
    __syncthreads();

    // Neumann solve (I - 0.25 G) x = rhs ; rho(0.25G) <= 0.25
    if (w == 0) {
        float gr[25];
        const float rh = (lane < 25) ? rhsS[lane] : 0.f;
        if (lane < 25) {
#pragma unroll
            for (int p = 0; p < 25; p++) gr[p] = Gm[lane*26 + p];
        }
        float xi = rh;
        xs[lane] = xi;
        for (int it = 0; it < 16; it++) {
            __syncwarp();
            float s = 0.f;
            if (lane < 25) {
#pragma unroll
                for (int p = 0; p < 25; p++) s += gr[p]*xs[p];
            }
            __syncwarp();
            xi = (lane < 25) ? rh + 0.25f*s : 0.f;
            xs[lane] = xi;
        }
        __syncwarp();
        float dv = xi;
        for (int o = 16; o; o >>= 1) dv += __shfl_xor_sync(0xffffffffu, dv, o);
        if (lane == 0) denomS[0] = dv;
    }
    __syncthreads();

    // predicts[w] = sum_{j in class w} (B x)_j / sum_i x_i
    if (w < 5) {
        float s = 0.f;
        for (int jj = lane; jj < 125; jj += 32) {
            const int j = w*125 + jj;
            float y = 0.f;
#pragma unroll
            for (int i = 0; i < 25; i++) y += T1[i*625 + j]*xs[i];
            s += y;
        }
        for (int o = 16; o; o >>= 1) s += __shfl_xor_sync(0xffffffffu, s, o);
        if (lane == 0) clsS[w] = s;
    }
    __syncthreads();
    if (t < 5) out[n*5 + t] = clsS[t] / denomS[0];
}

// =====================================================================
extern "C" void kernel_launch(void* const* d_in, const int* in_sizes, int n_in,
                              void* d_out, int out_size)
{
    const float* query   = (const float*)d_in[0];
    const float* support = (const float*)d_in[1];
    float* out = (float*)d_out;

    cudaFuncSetAttribute(post_kernel, cudaFuncAttributeMaxDynamicSharedMemorySize, POST_BYTES);
    cudaFuncSetAttribute(gemm_tf32_kernel, cudaFuncAttributeMaxDynamicSharedMemorySize, GSM_BYTES);

    transpose_norm_kernel<<<B_*25, 256>>>(support, 0);   // -> g_sT, g_sInv
    transpose_norm_kernel<<<B_*QN, 256>>>(query,   1);   // -> g_qT, g_qInv

    dim3 gg(5, 15, B_);   // n-tiles x m-tiles x batch
    gemm_tf32_kernel<<<gg, 256, GSM_BYTES>>>();

    post_kernel<<<NTOT, PNT, POST_BYTES>>>(out);
}

// round 9
// speedup vs baseline: 2.8780x; 1.1455x over previous
#include <cuda_runtime.h>
#include <cstdint>

// Problem constants (fixed by setup_inputs)
#define B_   16
#define QN   75
#define C_   640
#define HW   25
#define MS   625
#define NTOT (B_*QN)      // 1200
#define MPAD 1920         // 15*128 padded query rows per batch
#define NPAD 640          // 5*128 padded support rows per batch

// ---------------- scratch (device globals: allocation-free, zero-init) -----
// K-dimension stored PERMUTED within each 32-block: pos = (k%4)*8 + k/4
__device__ __align__(16) float g_qT[(size_t)B_*MPAD*C_];
__device__ __align__(16) float g_sT[(size_t)B_*NPAD*C_];
__device__ __align__(16) float g_qInv[B_*QN*HW];
__device__ __align__(16) float g_sInv[B_*MS];
__device__ __align__(16) float g_S[(size_t)NTOT*HW*MS];     // S[n][25][625]

// ======================= helpers ===========================================
__device__ __forceinline__ uint32_t smem_u32(const void* p) {
    uint32_t a;
    asm("{ .reg .u64 t; cvta.to.shared.u64 t, %1; cvt.u32.u64 %0, t; }" : "=r"(a) : "l"(p));
    return a;
}
__device__ __forceinline__ float to_tf32(float v) {
    uint32_t o;
    asm("cvt.rna.tf32.f32 %0, %1;" : "=r"(o) : "f"(v));
    return __uint_as_float(o);
}
__device__ __forceinline__ void cp16(uint32_t d, const void* s) {
    asm volatile("cp.async.cg.shared.global [%0], [%1], 16;" :: "r"(d), "l"(s));
}
// permute k within its 32-block: pos = (k%4)*8 + (k%32)/4
__device__ __forceinline__ int kperm(int k) {
    return (k & ~31) + ((k & 3) * 8) + ((k & 31) >> 2);
}

// =====================================================================
// K1: transpose (c-major -> row-contiguous) + norm + tf32 + k-permute.
// One block per image. mode 0: support, 1: query.
// =====================================================================
__global__ __launch_bounds__(256) void transpose_norm_kernel(const float* __restrict__ src, int mode)
{
    __shared__ float tile[320*25];
    const int t = threadIdx.x, w = t >> 5, lane = t & 31;
    const int bi = blockIdx.x;
    const int imgs_per_b = mode ? QN : (MS/HW);     // 75 or 25
    const int b = bi / imgs_per_b, im = bi % imgs_per_b;
    const size_t base = (size_t)bi * (C_*HW);

    float* dst = mode ? g_qT : g_sT;
    float* inv = mode ? g_qInv : g_sInv;
    const size_t padrow0 = (size_t)b * (mode ? MPAD : NPAD) + (size_t)im * HW;
    const size_t invrow0 = (size_t)b * (mode ? (QN*HW) : MS) + (size_t)im * HW;

    float ss[4] = {0.f, 0.f, 0.f, 0.f};
    for (int ch = 0; ch < 2; ch++) {
        const int c0 = ch * 320;   // multiple of 32, so kperm stays chunk-local
        __syncthreads();
        for (int idx = t; idx < 8000; idx += 256)
            tile[idx] = src[base + (size_t)c0*HW + idx];
        __syncthreads();
#pragma unroll
        for (int slot = 0; slot < 4; slot++) {
            int p = w + slot*8;
            if (p < 25) {
                float s = 0.f;
                float* drow = dst + (padrow0 + p)*C_ + c0;
                for (int c = lane; c < 320; c += 32) {
                    float v = tile[c*25 + p];   // stride 25: conflict-free
                    s += v*v;
                    drow[kperm(c)] = to_tf32(v);
                }
                ss[slot] += s;
            }
        }
    }
#pragma unroll
    for (int slot = 0; slot < 4; slot++) {
        int p = w + slot*8;
        if (p < 25) {
            float s = ss[slot];
            for (int o = 16; o; o >>= 1) s += __shfl_down_sync(0xffffffffu, s, o);
            if (lane == 0) {
                float nn = sqrtf(s);
                float d1 = fmaxf(nn, 1e-12f);
                inv[invrow0 + p] = 1.0f / (d1 * (1e-16f + nn/d1));
            }
        }
    }
}

// =====================================================================
// K2: tf32 mma.sync GEMM with permuted-K smem -> vectorized frag loads.
// 128x128 CTA tile, BK=32, 8 warps (2x4), 64x32 warp tiles.
// Thread (g,t4) reads 8 contiguous floats per row (2x LDS.128) covering
// all 4 k-steps. LDA=36 keeps float4 loads 16B-aligned + conflict-free.
// =====================================================================
#define LDA 36
#define GSM_BYTES (4*128*LDA*4)   // 73728

__global__ __launch_bounds__(256) void gemm_tf32_kernel()
{
    extern __shared__ float sm[];
    float* As = sm;                     // [2][128*LDA]
    float* Bs = sm + 2*128*LDA;         // [2][128*LDA]

    const int t = threadIdx.x;
    const int lane = t & 31, wid = t >> 5;
    const int warpM = wid >> 2, warpN = wid & 3;   // 2 x 4 warp grid
    const int g = lane >> 2, t4 = lane & 3;
    const int arow0 = blockIdx.y * 128, brow0 = blockIdx.x * 128;
    const int b = blockIdx.z;
    const int lrow = t >> 3, lc4 = t & 7;          // loader mapping

    const float* A  = g_qT + ((size_t)b*MPAD + arow0)*C_;
    const float* Bp = g_sT + ((size_t)b*NPAD + brow0)*C_;

    float acc[4][4][4];
#pragma unroll
    for (int i = 0; i < 4; i++)
#pragma unroll
        for (int j = 0; j < 4; j++)
#pragma unroll
            for (int k = 0; k < 4; k++) acc[i][j][k] = 0.f;

    auto issue = [&](int kc, int buf) {
        float* Ad = As + buf*(128*LDA);
        float* Bd = Bs + buf*(128*LDA);
        const float* Ag = A  + kc*32;
        const float* Bg = Bp + kc*32;
#pragma unroll
        for (int i = 0; i < 4; i++) {
            const int r = i*32 + lrow;
            cp16(smem_u32(Ad + r*LDA + lc4*4), Ag + (size_t)r*C_ + lc4*4);
            cp16(smem_u32(Bd + r*LDA + lc4*4), Bg + (size_t)r*C_ + lc4*4);
        }
        asm volatile("cp.async.commit_group;" ::: "memory");
    };

    issue(0, 0);
    issue(1, 1);

    for (int kc = 0; kc < 20; kc++) {
        if (kc < 19) asm volatile("cp.async.wait_group 1;" ::: "memory");
        else         asm volatile("cp.async.wait_group 0;" ::: "memory");
        __syncthreads();

        const float* Awp = As + (kc&1)*(128*LDA) + (size_t)(warpM*64 + g)*LDA + t4*8;
        const float* Bwp = Bs + (kc&1)*(128*LDA) + (size_t)(warpN*32 + g)*LDA + t4*8;
#pragma unroll
        for (int half = 0; half < 2; half++) {
            // aH[mf*2+rr]: row warpM*64 + mf*16 + rr*8 + g, 4 perm-k values
            float aH[8][4];
            float bH[4][4];
#pragma unroll
            for (int mf = 0; mf < 4; mf++)
#pragma unroll
                for (int rr = 0; rr < 2; rr++)
                    *(float4*)aH[mf*2+rr] =
                        *(const float4*)(Awp + (mf*16 + rr*8)*LDA + half*4);
#pragma unroll
            for (int nf = 0; nf < 4; nf++)
                *(float4*)bH[nf] = *(const float4*)(Bwp + (nf*8)*LDA + half*4);
            // within this float4: element m2 corresponds to k = ks*8 + t4 + (m2&1)*4,
            // ks = half*2 + m2/2
#pragma unroll
            for (int ks2 = 0; ks2 < 2; ks2++) {
#pragma unroll
                for (int mf = 0; mf < 4; mf++)
#pragma unroll
                    for (int nf = 0; nf < 4; nf++)
                        asm volatile(
                            "mma.sync.aligned.m16n8k8.row.col.f32.tf32.tf32.f32 "
                            "{%0,%1,%2,%3}, {%4,%5,%6,%7}, {%8,%9}, {%0,%1,%2,%3};"
                            : "+f"(acc[mf][nf][0]), "+f"(acc[mf][nf][1]),
                              "+f"(acc[mf][nf][2]), "+f"(acc[mf][nf][3])
                            : "r"(__float_as_uint(aH[mf*2+0][2*ks2])),
                              "r"(__float_as_uint(aH[mf*2+1][2*ks2])),
                              "r"(__float_as_uint(aH[mf*2+0][2*ks2+1])),
                              "r"(__float_as_uint(aH[mf*2+1][2*ks2+1])),
                              "r"(__float_as_uint(bH[nf][2*ks2])),
                              "r"(__float_as_uint(bH[nf][2*ks2+1])));
            }
        }
        __syncthreads();
        if (kc + 2 < 20) issue(kc + 2, kc & 1);
    }

    // epilogue: apply the two inverse norms, write valid region of S
    const float* qInvB = g_qInv + b*1875;
    const float* sInvB = g_sInv + b*625;
    float* Cout = g_S + (size_t)b*1875*625;
#pragma unroll
    for (int mf = 0; mf < 4; mf++) {
#pragma unroll
        for (int rr = 0; rr < 2; rr++) {
            const int r = arow0 + warpM*64 + mf*16 + g + rr*8;
            if (r >= 1875) continue;
            const float qv = qInvB[r];
            float* orow = Cout + (size_t)r*625;
#pragma unroll
            for (int nf = 0; nf < 4; nf++) {
                const int c = brow0 + warpN*32 + nf*8 + 2*t4;
                if (c < 625)     orow[c]   = acc[mf][nf][rr*2+0] * qv * sInvB[c];
                if (c + 1 < 625) orow[c+1] = acc[mf][nf][rr*2+1] * qv * sInvB[c+1];
            }
        }
    }
}

// =====================================================================
// K3: per-n postprocessing v2 — e10-only smem (68KB -> 2 CTAs/SM).
// Tsq/Tqs never materialized: normalizers folded into G/rhs/class sums.
//   G[i][p] = rinv[p] * sum_j cinv[j]*e10[i,j]*e10[p,j]^2
// =====================================================================
#define PNT 512
#define PNW 16
#define POST_FLOATS 17100
#define POST_BYTES  (POST_FLOATS*4)

__global__ __launch_bounds__(PNT) void post_kernel(float* __restrict__ out)
{
    extern __shared__ float sm[];
    float* S0   = sm;            // 15625: e10
    float* cinv = sm + 15625;    // 625
    float* rinv = sm + 16250;    // 32
    float* rhsS = sm + 16282;    // 32
    float* Gm   = sm + 16314;    // 650
    float* xs   = sm + 16964;    // 32
    float* zx   = sm + 16996;    // 32 : rinv[i]*xs[i]
    float* clsS = sm + 17028;    // 8
    float* denomS = sm + 17036;  // 1

    const int n = blockIdx.x;
    const int t = threadIdx.x, w = t >> 5, lane = t & 31;

    // pass 1: e10 = exp(10*S) (no max subtraction: |S|<=1 -> e^20 max, safe)
    const float* Sg = g_S + (size_t)n * 15625;
    for (int idx = t; idx < 15625; idx += PNT)
        S0[idx] = __expf(10.f * Sg[idx]);
    __syncthreads();

    // row sums of e20=e10^2 -> rinv (gamma=20 softmax denominators)
    for (int i = w; i < 25; i += PNW) {
        const float* row = S0 + i*625;
        float s = 0.f;
        for (int j = lane; j < 625; j += 32) { float v = row[j]; s += v*v; }
        for (int o = 16; o; o >>= 1) s += __shfl_xor_sync(0xffffffffu, s, o);
        if (lane == 0) rinv[i] = 1.f / s;
    }
    // col sums of e10 -> cinv (gamma2=10 softmax denominators)
    for (int j = t; j < 625; j += PNT) {
        float s = 0.f;
#pragma unroll
        for (int i = 0; i < 25; i++) s += S0[i*625 + j];
        cinv[j] = 1.f / s;
    }
    __syncthreads();

    // rhs[i] = 1 + 0.5 * sum_j Tqs[i][j] = 1 + 0.5*sum_j e10[i,j]*cinv[j]
    for (int i = w; i < 25; i += PNW) {
        const float* row = S0 + i*625;
        float s = 0.f;
        for (int j = lane; j < 625; j += 32) s += row[j]*cinv[j];
        for (int o = 16; o; o >>= 1) s += __shfl_xor_sync(0xffffffffu, s, o);
        if (lane == 0) rhsS[i] = 1.f + 0.5f*s;
    }
    // G: 5x5 warp tiles; raw[i][p] = sum_j cinv[j]*e10[i,j]*e10[p,j]^2
    for (int tile = w; tile < 25; tile += PNW) {
        const int i0 = (tile/5)*5, p0 = (tile%5)*5;
        float acc[25];
#pragma unroll
        for (int z = 0; z < 25; z++) acc[z] = 0.f;
        for (int j = lane; j < 625; j += 32) {
            const float cj = cinv[j];
            float a[5], c2[5];
#pragma unroll
            for (int z = 0; z < 5; z++) {
                a[z]  = S0[(i0+z)*625 + j] * cj;
                float cv = S0[(p0+z)*625 + j];
                c2[z] = cv * cv;
            }
#pragma unroll
            for (int u = 0; u < 5; u++)
#pragma unroll
                for (int v = 0; v < 5; v++) acc[u*5+v] += a[u]*c2[v];
        }
#pragma unroll
        for (int z = 0; z < 25; z++) {
            float s = acc[z];
            for (int o = 16; o; o >>= 1) s += __shfl_xor_sync(0xffffffffu, s, o);
            if (lane == 0) Gm[(i0 + z/5)*26 + (p0 + z%5)] = s * rinv[p0 + z%5];
        }
    }
    __syncthreads();

    // Neumann solve (I - 0.25 G) x = rhs ; rho(0.25G) <= 0.25
    if (w == 0) {
        float gr[25];
        const float rh = (lane < 25) ? rhsS[lane] : 0.f;
        if (lane < 25) {
#pragma unroll
            for (int p = 0; p < 25; p++) gr[p] = Gm[lane*26 + p];
        }
        float xi = rh;
        xs[lane] = xi;
        for (int it = 0; it < 16; it++) {
            __syncwarp();
            float s = 0.f;
            if (lane < 25) {
#pragma unroll
                for (int p = 0; p < 25; p++) s += gr[p]*xs[p];
            }
            __syncwarp();
            xi = (lane < 25) ? rh + 0.25f*s : 0.f;
            xs[lane] = xi;
        }
        __syncwarp();
        float dv = xi;
        for (int o = 16; o; o >>= 1) dv += __shfl_xor_sync(0xffffffffu, dv, o);
        if (lane == 0) denomS[0] = dv;
        // zx[i] = rinv[i]*xs[i] for the class-sum pass
        if (lane < 25) zx[lane] = rinv[lane] * xi;
        else if (lane < 32) zx[lane] = 0.f;
    }
    __syncthreads();

    // predicts[w] = sum_{j in class w} sum_i e10[i,j]^2 * zx[i]  / denom
    if (w < 5) {
        float s = 0.f;
        for (int jj = lane; jj < 125; jj += 32) {
            const int j = w*125 + jj;
            float y = 0.f;
#pragma unroll
            for (int i = 0; i < 25; i++) {
                const float v = S0[i*625 + j];
                y += v*v*zx[i];
            }
            s += y;
        }
        for (int o = 16; o; o >>= 1) s += __shfl_xor_sync(0xffffffffu, s, o);
        if (lane == 0) clsS[w] = s;
    }
    __syncthreads();
    if (t < 5) out[n*5 + t] = clsS[t] / denomS[0];
}

// =====================================================================
extern "C" void kernel_launch(void* const* d_in, const int* in_sizes, int n_in,
                              void* d_out, int out_size)
{
    const float* query   = (const float*)d_in[0];
    const float* support = (const float*)d_in[1];
    float* out = (float*)d_out;

    cudaFuncSetAttribute(post_kernel, cudaFuncAttributeMaxDynamicSharedMemorySize, POST_BYTES);
    cudaFuncSetAttribute(gemm_tf32_kernel, cudaFuncAttributeMaxDynamicSharedMemorySize, GSM_BYTES);

    transpose_norm_kernel<<<B_*25, 256>>>(support, 0);   // -> g_sT, g_sInv
    transpose_norm_kernel<<<B_*QN, 256>>>(query,   1);   // -> g_qT, g_qInv

    dim3 gg(5, 15, B_);   // n-tiles x m-tiles x batch
    gemm_tf32_kernel<<<gg, 256, GSM_BYTES>>>();

    post_kernel<<<NTOT, PNT, POST_BYTES>>>(out);
}

// round 10
// speedup vs baseline: 2.9262x; 1.0168x over previous
#include <cuda_runtime.h>
#include <cstdint>

// Problem constants (fixed by setup_inputs)
#define B_   16
#define QN   75
#define C_   640
#define HW   25
#define MS   625
#define NTOT (B_*QN)      // 1200
#define MPAD 1920         // 15*128 padded query rows per batch
#define NPAD 640          // 5*128 padded support rows per batch

// ---------------- scratch (device globals: allocation-free, zero-init) -----
// K-dimension stored PERMUTED within each 32-block: pos = (k%4)*8 + k/4
__device__ __align__(16) float g_qT[(size_t)B_*MPAD*C_];
__device__ __align__(16) float g_sT[(size_t)B_*NPAD*C_];
__device__ __align__(16) float g_qInv[B_*QN*HW];
__device__ __align__(16) float g_sInv[B_*MS];
__device__ __align__(16) float g_S[(size_t)NTOT*HW*MS];     // S[n][25][625]

// ======================= helpers ===========================================
__device__ __forceinline__ uint32_t smem_u32(const void* p) {
    uint32_t a;
    asm("{ .reg .u64 t; cvta.to.shared.u64 t, %1; cvt.u32.u64 %0, t; }" : "=r"(a) : "l"(p));
    return a;
}
__device__ __forceinline__ float to_tf32(float v) {
    uint32_t o;
    asm("cvt.rna.tf32.f32 %0, %1;" : "=r"(o) : "f"(v));
    return __uint_as_float(o);
}
__device__ __forceinline__ void cp16(uint32_t d, const void* s) {
    asm volatile("cp.async.cg.shared.global [%0], [%1], 16;" :: "r"(d), "l"(s));
}
// permute k within its 32-block: pos = (k%4)*8 + (k%32)/4
__device__ __forceinline__ int kperm(int k) {
    return (k & ~31) + ((k & 3) * 8) + ((k & 31) >> 2);
}

// =====================================================================
// K1: transpose (c-major -> row-contiguous) + norm + tf32 + k-permute.
// One block per image. mode 0: support, 1: query.
// =====================================================================
__global__ __launch_bounds__(256) void transpose_norm_kernel(const float* __restrict__ src, int mode)
{
    __shared__ float tile[320*25];
    const int t = threadIdx.x, w = t >> 5, lane = t & 31;
    const int bi = blockIdx.x;
    const int imgs_per_b = mode ? QN : (MS/HW);     // 75 or 25
    const int b = bi / imgs_per_b, im = bi % imgs_per_b;
    const size_t base = (size_t)bi * (C_*HW);

    float* dst = mode ? g_qT : g_sT;
    float* inv = mode ? g_qInv : g_sInv;
    const size_t padrow0 = (size_t)b * (mode ? MPAD : NPAD) + (size_t)im * HW;
    const size_t invrow0 = (size_t)b * (mode ? (QN*HW) : MS) + (size_t)im * HW;

    float ss[4] = {0.f, 0.f, 0.f, 0.f};
    for (int ch = 0; ch < 2; ch++) {
        const int c0 = ch * 320;   // multiple of 32, so kperm stays chunk-local
        __syncthreads();
        for (int idx = t; idx < 8000; idx += 256)
            tile[idx] = src[base + (size_t)c0*HW + idx];
        __syncthreads();
#pragma unroll
        for (int slot = 0; slot < 4; slot++) {
            int p = w + slot*8;
            if (p < 25) {
                float s = 0.f;
                float* drow = dst + (padrow0 + p)*C_ + c0;
                for (int c = lane; c < 320; c += 32) {
                    float v = tile[c*25 + p];   // stride 25: conflict-free
                    s += v*v;
                    drow[kperm(c)] = to_tf32(v);
                }
                ss[slot] += s;
            }
        }
    }
#pragma unroll
    for (int slot = 0; slot < 4; slot++) {
        int p = w + slot*8;
        if (p < 25) {
            float s = ss[slot];
            for (int o = 16; o; o >>= 1) s += __shfl_down_sync(0xffffffffu, s, o);
            if (lane == 0) {
                float nn = sqrtf(s);
                float d1 = fmaxf(nn, 1e-12f);
                inv[invrow0 + p] = 1.0f / (d1 * (1e-16f + nn/d1));
            }
        }
    }
}

// =====================================================================
// K2: tf32 mma.sync GEMM, 3-stage cp.async pipeline, ONE sync/iter.
// 128x128 CTA tile, BK=32, 8 warps (2x4), 64x32 warp tiles,
// permuted-K smem -> float4 frag loads. 110.6KB smem -> 2 CTAs/SM.
// =====================================================================
#define LDA 36
#define STG_FLOATS (128*LDA)
#define GSM_BYTES (3*2*STG_FLOATS*4)   // 110592

__global__ __launch_bounds__(256, 2) void gemm_tf32_kernel()
{
    extern __shared__ float sm[];
    float* As = sm;                      // [3][128*LDA]
    float* Bs = sm + 3*STG_FLOATS;       // [3][128*LDA]

    const int t = threadIdx.x;
    const int lane = t & 31, wid = t >> 5;
    const int warpM = wid >> 2, warpN = wid & 3;   // 2 x 4 warp grid
    const int g = lane >> 2, t4 = lane & 3;
    const int arow0 = blockIdx.y * 128, brow0 = blockIdx.x * 128;
    const int b = blockIdx.z;
    const int lrow = t >> 3, lc4 = t & 7;          // loader mapping

    const float* A  = g_qT + ((size_t)b*MPAD + arow0)*C_;
    const float* Bp = g_sT + ((size_t)b*NPAD + brow0)*C_;

    float acc[4][4][4];
#pragma unroll
    for (int i = 0; i < 4; i++)
#pragma unroll
        for (int j = 0; j < 4; j++)
#pragma unroll
            for (int k = 0; k < 4; k++) acc[i][j][k] = 0.f;

    auto issue = [&](int kc, int buf) {
        float* Ad = As + buf*STG_FLOATS;
        float* Bd = Bs + buf*STG_FLOATS;
        const float* Ag = A  + kc*32;
        const float* Bg = Bp + kc*32;
#pragma unroll
        for (int i = 0; i < 4; i++) {
            const int r = i*32 + lrow;
            cp16(smem_u32(Ad + r*LDA + lc4*4), Ag + (size_t)r*C_ + lc4*4);
            cp16(smem_u32(Bd + r*LDA + lc4*4), Bg + (size_t)r*C_ + lc4*4);
        }
        asm volatile("cp.async.commit_group;" ::: "memory");
    };

    issue(0, 0);
    issue(1, 1);

    for (int kc = 0; kc < 20; kc++) {
        // group G_kc complete <=> at most 1 newer group outstanding
        if (kc < 19) asm volatile("cp.async.wait_group 1;" ::: "memory");
        else         asm volatile("cp.async.wait_group 0;" ::: "memory");
        __syncthreads();
        // safe: buffer (kc+2)%3 == (kc-1)%3, consumed by ALL warps before this sync
        if (kc + 2 < 20) issue(kc + 2, (kc + 2) % 3);

        const int cbuf = kc % 3;
        const float* Awp = As + cbuf*STG_FLOATS + (size_t)(warpM*64 + g)*LDA + t4*8;
        const float* Bwp = Bs + cbuf*STG_FLOATS + (size_t)(warpN*32 + g)*LDA + t4*8;
#pragma unroll
        for (int half = 0; half < 2; half++) {
            float aH[8][4];
            float bH[4][4];
#pragma unroll
            for (int mf = 0; mf < 4; mf++)
#pragma unroll
                for (int rr = 0; rr < 2; rr++)
                    *(float4*)aH[mf*2+rr] =
                        *(const float4*)(Awp + (mf*16 + rr*8)*LDA + half*4);
#pragma unroll
            for (int nf = 0; nf < 4; nf++)
                *(float4*)bH[nf] = *(const float4*)(Bwp + (nf*8)*LDA + half*4);
#pragma unroll
            for (int ks2 = 0; ks2 < 2; ks2++) {
#pragma unroll
                for (int mf = 0; mf < 4; mf++)
#pragma unroll
                    for (int nf = 0; nf < 4; nf++)
                        asm volatile(
                            "mma.sync.aligned.m16n8k8.row.col.f32.tf32.tf32.f32 "
                            "{%0,%1,%2,%3}, {%4,%5,%6,%7}, {%8,%9}, {%0,%1,%2,%3};"
                            : "+f"(acc[mf][nf][0]), "+f"(acc[mf][nf][1]),
                              "+f"(acc[mf][nf][2]), "+f"(acc[mf][nf][3])
                            : "r"(__float_as_uint(aH[mf*2+0][2*ks2])),
                              "r"(__float_as_uint(aH[mf*2+1][2*ks2])),
                              "r"(__float_as_uint(aH[mf*2+0][2*ks2+1])),
                              "r"(__float_as_uint(aH[mf*2+1][2*ks2+1])),
                              "r"(__float_as_uint(bH[nf][2*ks2])),
                              "r"(__float_as_uint(bH[nf][2*ks2+1])));
            }
        }
    }

    // epilogue: apply the two inverse norms, write valid region of S
    const float* qInvB = g_qInv + b*1875;
    const float* sInvB = g_sInv + b*625;
    float* Cout = g_S + (size_t)b*1875*625;
#pragma unroll
    for (int mf = 0; mf < 4; mf++) {
#pragma unroll
        for (int rr = 0; rr < 2; rr++) {
            const int r = arow0 + warpM*64 + mf*16 + g + rr*8;
            if (r >= 1875) continue;
            const float qv = qInvB[r];
            float* orow = Cout + (size_t)r*625;
#pragma unroll
            for (int nf = 0; nf < 4; nf++) {
                const int c = brow0 + warpN*32 + nf*8 + 2*t4;
                if (c < 625)     orow[c]   = acc[mf][nf][rr*2+0] * qv * sInvB[c];
                if (c + 1 < 625) orow[c+1] = acc[mf][nf][rr*2+1] * qv * sInvB[c+1];
            }
        }
    }
}

// =====================================================================
// K3: per-n postprocessing v4 — column-parallel pass1 fuses the column
// sums; rhs fused into the G pass. 3 S0 sweeps total (was 5).
// =====================================================================
#define PNT 640
#define PNW 20
#define POST_FLOATS 17100
#define POST_BYTES  (POST_FLOATS*4)

__global__ __launch_bounds__(PNT, 2) void post_kernel(float* __restrict__ out)
{
    extern __shared__ float sm[];
    float* S0   = sm;            // 15625: e10
    float* cinv = sm + 15625;    // 625
    float* rinv = sm + 16250;    // 32
    float* rhsS = sm + 16282;    // 32
    float* Gm   = sm + 16314;    // 650
    float* xs   = sm + 16964;    // 32
    float* zx   = sm + 16996;    // 32 : rinv[i]*xs[i]
    float* clsS = sm + 17028;    // 8
    float* denomS = sm + 17036;  // 1

    const int n = blockIdx.x;
    const int t = threadIdx.x, w = t >> 5, lane = t & 31;

    // pass 1 (column-parallel): e10 = exp(10*S), column sums inline -> cinv
    const float* Sg = g_S + (size_t)n * 15625;
    if (t < 625) {
        float cs = 0.f;
#pragma unroll
        for (int i = 0; i < 25; i++) {
            const float e = __expf(10.f * Sg[i*625 + t]);
            S0[i*625 + t] = e;
            cs += e;
        }
        cinv[t] = 1.f / cs;
    }
    __syncthreads();

    // row sums of e20 = e10^2 -> rinv (gamma=20 softmax denominators)
    for (int i = w; i < 25; i += PNW) {
        const float* row = S0 + i*625;
        float s = 0.f;
        for (int j = lane; j < 625; j += 32) { float v = row[j]; s += v*v; }
        for (int o = 16; o; o >>= 1) s += __shfl_xor_sync(0xffffffffu, s, o);
        if (lane == 0) rinv[i] = 1.f / s;
    }
    __syncthreads();

    // G (+ fused rhs): raw[i][p] = sum_j cinv[j]*e10[i,j]*e10[p,j]^2
    // rhs[i] = 1 + 0.5*sum_j cinv[j]*e10[i,j], computed in the p0==0 tiles
    for (int tile = w; tile < 25; tile += PNW) {
        const int i0 = (tile/5)*5, p0 = (tile%5)*5;
        float acc[25], racc[5];
#pragma unroll
        for (int z = 0; z < 25; z++) acc[z] = 0.f;
#pragma unroll
        for (int z = 0; z < 5; z++) racc[z] = 0.f;
        for (int j = lane; j < 625; j += 32) {
            const float cj = cinv[j];
            float a[5], c2[5];
#pragma unroll
            for (int z = 0; z < 5; z++) {
                a[z]  = S0[(i0+z)*625 + j] * cj;
                float cv = S0[(p0+z)*625 + j];
                c2[z] = cv * cv;
            }
            if (p0 == 0) {
#pragma unroll
                for (int z = 0; z < 5; z++) racc[z] += a[z];
            }
#pragma unroll
            for (int u = 0; u < 5; u++)
#pragma unroll
                for (int v = 0; v < 5; v++) acc[u*5+v] += a[u]*c2[v];
        }
#pragma unroll
        for (int z = 0; z < 25; z++) {
            float s = acc[z];
            for (int o = 16; o; o >>= 1) s += __shfl_xor_sync(0xffffffffu, s, o);
            if (lane == 0) Gm[(i0 + z/5)*26 + (p0 + z%5)] = s * rinv[p0 + z%5];
        }
        if (p0 == 0) {
#pragma unroll
            for (int z = 0; z < 5; z++) {
                float s = racc[z];
                for (int o = 16; o; o >>= 1) s += __shfl_xor_sync(0xffffffffu, s, o);
                if (lane == 0) rhsS[i0 + z] = 1.f + 0.5f*s;
            }
        }
    }
    __syncthreads();

    // Neumann solve (I - 0.25 G) x = rhs ; rho(0.25G) <= 0.25
    if (w == 0) {
        float gr[25];
        const float rh = (lane < 25) ? rhsS[lane] : 0.f;
        if (lane < 25) {
#pragma unroll
            for (int p = 0; p < 25; p++) gr[p] = Gm[lane*26 + p];
        }
        float xi = rh;
        xs[lane] = xi;
        for (int it = 0; it < 16; it++) {
            __syncwarp();
            float s = 0.f;
            if (lane < 25) {
#pragma unroll
                for (int p = 0; p < 25; p++) s += gr[p]*xs[p];
            }
            __syncwarp();
            xi = (lane < 25) ? rh + 0.25f*s : 0.f;
            xs[lane] = xi;
        }
        __syncwarp();
        float dv = xi;
        for (int o = 16; o; o >>= 1) dv += __shfl_xor_sync(0xffffffffu, dv, o);
        if (lane == 0) denomS[0] = dv;
        if (lane < 25) zx[lane] = rinv[lane] * xi;
        else if (lane < 32) zx[lane] = 0.f;
    }
    __syncthreads();

    // predicts[w] = sum_{j in class w} sum_i e10[i,j]^2 * zx[i]  / denom
    if (w < 5) {
        float s = 0.f;
        for (int jj = lane; jj < 125; jj += 32) {
            const int j = w*125 + jj;
            float y = 0.f;
#pragma unroll
            for (int i = 0; i < 25; i++) {
                const float v = S0[i*625 + j];
                y += v*v*zx[i];
            }
            s += y;
        }
        for (int o = 16; o; o >>= 1) s += __shfl_xor_sync(0xffffffffu, s, o);
        if (lane == 0) clsS[w] = s;
    }
    __syncthreads();
    if (t < 5) out[n*5 + t] = clsS[t] / denomS[0];
}

// =====================================================================
extern "C" void kernel_launch(void* const* d_in, const int* in_sizes, int n_in,
                              void* d_out, int out_size)
{
    const float* query   = (const float*)d_in[0];
    const float* support = (const float*)d_in[1];
    float* out = (float*)d_out;

    cudaFuncSetAttribute(post_kernel, cudaFuncAttributeMaxDynamicSharedMemorySize, POST_BYTES);
    cudaFuncSetAttribute(gemm_tf32_kernel, cudaFuncAttributeMaxDynamicSharedMemorySize, GSM_BYTES);

    transpose_norm_kernel<<<B_*25, 256>>>(support, 0);   // -> g_sT, g_sInv
    transpose_norm_kernel<<<B_*QN, 256>>>(query,   1);   // -> g_qT, g_qInv

    dim3 gg(5, 15, B_);   // n-tiles x m-tiles x batch
    gemm_tf32_kernel<<<gg, 256, GSM_BYTES>>>();

    post_kernel<<<NTOT, PNT, POST_BYTES>>>(out);
}